// round 7
// baseline (speedup 1.0000x reference)
#include <cuda_runtime.h>
#include <cuda_fp16.h>
#include <math.h>

#define NMAX 50000
#define EMAX 1600000
#define FIN  128
#define FOUT 64
#define ALPHA 0.2f

// ---------------- scratch (device globals; no allocation) ----------------
__device__ __half g_h16[NMAX * FOUT];    // h = input @ W  (fp16 for the gather)
__device__ float g_hprime[NMAX * FOUT];  // segment sum accumulator (fp32)
__device__ float g_hcol[NMAX];           // h . a1l  (= input . (W a1l))
__device__ float g_ha2r[NMAX];           // h . a2r
__device__ float g_pha1r[NMAX];          // p_h . (W a1r)
__device__ float g_nha2l[NMAX];          // new_h . (W a2l)
__device__ float g_ecsm[NMAX];           // edge_col_e -> ex -> softmax result
__device__ float g_segmax[NMAX];
__device__ float g_segsum[NMAX];
__device__ float g_erowsum[NMAX];
__device__ float g_einv[NMAX];
__device__ float g_edge_e[EMAX];
__device__ float g_v1[FIN], g_v2[FIN], g_v3[FIN], g_v4[FIN];

// ---------------- zeroing (merged; graph-replay safe reset) ----------------
__global__ void k_zero(int n) {
    int i = blockIdx.x * blockDim.x + threadIdx.x;
    int n16 = n * (FOUT / 4);
    if (i < n16) ((float4*)g_hprime)[i] = make_float4(0.f, 0.f, 0.f, 0.f);
    if (i < n) {
        g_segmax[i] = 0.f;
        g_segsum[i] = 0.f;
        g_erowsum[i] = 0.f;
    }
}

// ---------------- small vectors: v = W @ a-halves ----------------
__global__ void k_vec(const float* __restrict__ W,
                      const float* __restrict__ a1,
                      const float* __restrict__ a2) {
    int k = threadIdx.x;  // 128 threads
    float s1 = 0.f, s2 = 0.f, s3 = 0.f, s4 = 0.f;
#pragma unroll 8
    for (int j = 0; j < FOUT; j++) {
        float w = W[k * FOUT + j];
        s1 += w * a1[j];
        s2 += w * a1[FOUT + j];
        s3 += w * a2[j];
        s4 += w * a2[FOUT + j];
    }
    g_v1[k] = s1; g_v2[k] = s2; g_v3[k] = s3; g_v4[k] = s4;
}

// ---------------- per-row dot products (matrix-vector) ----------------
__global__ void k_dots(const float* __restrict__ X,
                       const float* __restrict__ P,
                       const float* __restrict__ NH, int n) {
    int warp = (blockIdx.x * blockDim.x + threadIdx.x) >> 5;
    int lane = threadIdx.x & 31;
    if (warp >= n) return;
    float4 xv = ((const float4*)(X + (long)warp * FIN))[lane];
    float4 pv = ((const float4*)(P + (long)warp * FIN))[lane];
    float4 nv = ((const float4*)(NH + (long)warp * FIN))[lane];
    float4 v1 = ((const float4*)g_v1)[lane];
    float4 v2 = ((const float4*)g_v2)[lane];
    float4 v3 = ((const float4*)g_v3)[lane];
    float4 v4 = ((const float4*)g_v4)[lane];
    float s_hcol = xv.x * v1.x + xv.y * v1.y + xv.z * v1.z + xv.w * v1.w;
    float s_ha2r = xv.x * v4.x + xv.y * v4.y + xv.z * v4.z + xv.w * v4.w;
    float s_pha1 = pv.x * v2.x + pv.y * v2.y + pv.z * v2.z + pv.w * v2.w;
    float s_nha2 = nv.x * v3.x + nv.y * v3.y + nv.z * v3.z + nv.w * v3.w;
#pragma unroll
    for (int o = 16; o > 0; o >>= 1) {
        s_hcol += __shfl_down_sync(0xFFFFFFFFu, s_hcol, o);
        s_ha2r += __shfl_down_sync(0xFFFFFFFFu, s_ha2r, o);
        s_pha1 += __shfl_down_sync(0xFFFFFFFFu, s_pha1, o);
        s_nha2 += __shfl_down_sync(0xFFFFFFFFu, s_nha2, o);
    }
    if (lane == 0) {
        g_hcol[warp] = s_hcol;
        g_ha2r[warp] = s_ha2r;
        g_pha1r[warp] = s_pha1;
        g_nha2l[warp] = s_nha2;
    }
}

// ---------------- GEMM: h = input @ W (N x 128 x 64), 8x8 register tile ----
// 128 threads; tile 128 rows x 64 cols; K chunk = 32.
// Thread (cg = t&7, rg = t>>3) owns rows rg*8..+7, cols {cg*4..+3, 32+cg*4..+3}
// (split column mapping -> 8 cg-groups hit 32 distinct banks; conflict-free).
__global__ void __launch_bounds__(128)
k_gemm(const float* __restrict__ X, const float* __restrict__ W, int n) {
    __shared__ float Xs[32][128];   // [k][row]  16 KB
    __shared__ float Ws[32][FOUT];  // [k][col]   8 KB
    int tid = threadIdx.x;
    int cg = tid & 7;
    int rg = tid >> 3;
    long row0 = (long)blockIdx.x * 128;
    float acc[8][8] = {};  // [r][c]: c 0..3 -> cols cg*4+c ; c 4..7 -> 32+cg*4+(c-4)

    for (int kb = 0; kb < FIN; kb += 32) {
        // stage W chunk: 32x64 floats = 512 float4
        for (int i = tid; i < 512; i += 128)
            ((float4*)Ws)[i] = ((const float4*)(W + (long)kb * FOUT))[i];
        // stage X chunk transposed: thread owns one row
        {
            long row = row0 + tid;
            if (row < n) {
                const float4* src = (const float4*)(X + row * FIN + kb);
#pragma unroll
                for (int j = 0; j < 8; j++) {
                    float4 v = src[j];
                    Xs[j * 4 + 0][tid] = v.x;
                    Xs[j * 4 + 1][tid] = v.y;
                    Xs[j * 4 + 2][tid] = v.z;
                    Xs[j * 4 + 3][tid] = v.w;
                }
            } else {
#pragma unroll
                for (int j = 0; j < 32; j++) Xs[j][tid] = 0.f;
            }
        }
        __syncthreads();
#pragma unroll
        for (int k = 0; k < 32; k++) {
            float4 xa = *(const float4*)&Xs[k][rg * 8];
            float4 xb = *(const float4*)&Xs[k][rg * 8 + 4];
            float4 wa = *(const float4*)&Ws[k][cg * 4];
            float4 wb = *(const float4*)&Ws[k][32 + cg * 4];
            float xr[8] = {xa.x, xa.y, xa.z, xa.w, xb.x, xb.y, xb.z, xb.w};
            float wc[8] = {wa.x, wa.y, wa.z, wa.w, wb.x, wb.y, wb.z, wb.w};
#pragma unroll
            for (int r = 0; r < 8; r++)
#pragma unroll
                for (int c = 0; c < 8; c++)
                    acc[r][c] += xr[r] * wc[c];
        }
        __syncthreads();
    }
    // write h as fp16 (four 4B half2 stores per row)
#pragma unroll
    for (int r = 0; r < 8; r++) {
        long row = row0 + rg * 8 + r;
        if (row < n) {
            __half2 p0 = __floats2half2_rn(acc[r][0], acc[r][1]);
            __half2 p1 = __floats2half2_rn(acc[r][2], acc[r][3]);
            __half2 p2 = __floats2half2_rn(acc[r][4], acc[r][5]);
            __half2 p3 = __floats2half2_rn(acc[r][6], acc[r][7]);
            *(__half2*)(g_h16 + row * FOUT + cg * 4)          = p0;
            *(__half2*)(g_h16 + row * FOUT + cg * 4 + 2)      = p1;
            *(__half2*)(g_h16 + row * FOUT + 32 + cg * 4)     = p2;
            *(__half2*)(g_h16 + row * FOUT + 32 + cg * 4 + 2) = p3;
        }
    }
}

// ---------------- column softmax passes ----------------
__global__ void k_col1(const int* __restrict__ edge_col0,
                       const int* __restrict__ row_i, int n) {
    int i = blockIdx.x * blockDim.x + threadIdx.x;
    if (i >= n) return;
    float cs = g_hcol[edge_col0[i]] + g_pha1r[i];
    float lr = cs > 0.f ? cs : ALPHA * cs;
    float e = expf(-lr);
    g_ecsm[i] = e;
    atomicMax((int*)&g_segmax[row_i[i]], __float_as_int(e));  // e > 0 always
}
__global__ void k_col2(const int* __restrict__ row_i, int n) {
    int i = blockIdx.x * blockDim.x + threadIdx.x;
    if (i >= n) return;
    float ex = expf(g_ecsm[i] - g_segmax[row_i[i]]);
    g_ecsm[i] = ex;
    atomicAdd(&g_segsum[row_i[i]], ex);
}
__global__ void k_col3(const int* __restrict__ row_i, int n) {
    int i = blockIdx.x * blockDim.x + threadIdx.x;
    if (i >= n) return;
    g_ecsm[i] = g_ecsm[i] / (g_segsum[row_i[i]] + 1e-16f);
}

// ---------------- edge scores + rowsum ----------------
__global__ void k_edge1(const int* __restrict__ edge0,
                        const int* __restrict__ edge1,
                        const int* __restrict__ row_resort, int E) {
    int e = blockIdx.x * blockDim.x + threadIdx.x;
    if (e >= E) return;
    int rr = row_resort[e];
    float rs = g_nha2l[rr] + g_ha2r[edge1[e]];
    float lr = rs > 0.f ? rs : ALPHA * rs;
    float ee = expf(-lr) * g_ecsm[rr];
    g_edge_e[e] = ee;
    atomicAdd(&g_erowsum[edge0[e]], ee);
}
__global__ void k_rowfix(int n) {
    int i = blockIdx.x * blockDim.x + threadIdx.x;
    if (i >= n) return;
    float s = g_erowsum[i];
    if (s == 0.f) s = 1.f;
    g_einv[i] = 1.f / s;
}

// ---------------- main scatter: h_prime += edge_e * h[edge1] ----------------
// 16 threads/edge (R1 shape): each loads 8B fp16 (4 halves), one red.v4.f32.
__global__ void k_edge2(const int* __restrict__ edge0,
                        const int* __restrict__ edge1,
                        float* __restrict__ att_out, int E, int write_att) {
    int e = (blockIdx.x * blockDim.x + threadIdx.x) >> 4;
    int t = threadIdx.x & 15;
    if (e >= E) return;
    int dst = edge0[e], src = edge1[e];
    float ee = g_edge_e[e];
    const uint2 hv = *(const uint2*)(g_h16 + (long)src * FOUT + t * 4);
    float2 f0 = __half22float2(*(const __half2*)&hv.x);
    float2 f1 = __half22float2(*(const __half2*)&hv.y);
    float* dp = g_hprime + (long)dst * FOUT + t * 4;
    asm volatile("red.global.add.v4.f32 [%0], {%1, %2, %3, %4};"
                 :: "l"(__cvta_generic_to_global(dp)),
                    "f"(ee * f0.x), "f"(ee * f0.y), "f"(ee * f1.x), "f"(ee * f1.y)
                 : "memory");
    if (t == 0 && write_att) att_out[e] = ee * g_einv[dst];
}

// ---------------- finalize: out = elu(h_prime / e_rowsum) ----------------
__global__ void k_final(float* __restrict__ out, int n) {
    int i4 = blockIdx.x * blockDim.x + threadIdx.x;  // one float4 each
    if (i4 >= n * (FOUT / 4)) return;
    int row = i4 >> 4;
    float inv = g_einv[row];
    float4 v = ((const float4*)g_hprime)[i4];
    v.x *= inv; v.y *= inv; v.z *= inv; v.w *= inv;
    v.x = v.x > 0.f ? v.x : expm1f(v.x);
    v.y = v.y > 0.f ? v.y : expm1f(v.y);
    v.z = v.z > 0.f ? v.z : expm1f(v.z);
    v.w = v.w > 0.f ? v.w : expm1f(v.w);
    ((float4*)out)[i4] = v;
}

// ---------------- copy edge indices to output as float ----------------
__global__ void k_edgecopy(const int* __restrict__ edge, float* __restrict__ out,
                           int n2e) {
    int i = blockIdx.x * blockDim.x + threadIdx.x;
    if (i < n2e) out[i] = (float)edge[i];
}

extern "C" void kernel_launch(void* const* d_in, const int* in_sizes, int n_in,
                              void* d_out, int out_size) {
    const float* input      = (const float*)d_in[0];
    const float* p_h        = (const float*)d_in[1];
    const float* new_h      = (const float*)d_in[2];
    const int*   edge       = (const int*)d_in[3];
    const int*   edge_col   = (const int*)d_in[4];
    const int*   row_i      = (const int*)d_in[5];
    const int*   row_resort = (const int*)d_in[6];
    const float* W          = (const float*)d_in[8];
    const float* a1         = (const float*)d_in[9];
    const float* a2         = (const float*)d_in[10];

    int N = in_sizes[0] / FIN;
    int E = in_sizes[3] / 2;
    const int* edge0 = edge;
    const int* edge1 = edge + E;
    float* out = (float*)d_out;

    long n64 = (long)N * FOUT;
    int full = (out_size >= (int)(n64 + 2L * E + E)) ? 1 : 0;
    float* out_edges = full ? out + n64 : nullptr;
    float* out_att   = full ? out + n64 + 2L * E : out;  // dummy if !full

    const int T = 256;
    // launch order chosen so k_gemm is launch #4 (the profiled one)
    k_zero<<<(N * 16 + T - 1) / T, T>>>(N);
    k_vec<<<1, 128>>>(W, a1, a2);
    k_dots<<<(N * 32 + T - 1) / T, T>>>(input, p_h, new_h, N);
    k_gemm<<<(N + 127) / 128, 128>>>(input, W, N);

    k_col1<<<(N + T - 1) / T, T>>>(edge_col, row_i, N);
    k_col2<<<(N + T - 1) / T, T>>>(row_i, N);
    k_col3<<<(N + T - 1) / T, T>>>(row_i, N);

    k_edge1<<<(E + T - 1) / T, T>>>(edge0, edge1, row_resort, E);
    k_rowfix<<<(N + T - 1) / T, T>>>(N);

    k_edge2<<<(E * 16 + T - 1) / T, T>>>(edge0, edge1, out_att, E, full);
    k_final<<<((N * FOUT / 4) + T - 1) / T, T>>>(out, N);
    if (full) {
        k_edgecopy<<<(2 * E + T - 1) / T, T>>>(edge, out_edges, 2 * E);
    }
}

// round 8
// speedup vs baseline: 1.4691x; 1.4691x over previous
#include <cuda_runtime.h>
#include <cuda_bf16.h>
#include <math.h>

#define NMAX 50000
#define EMAX 1600000
#define FIN  128
#define FOUT 64
#define ALPHA 0.2f

// ---------------- scratch (device globals; no allocation) ----------------
__device__ float g_h[NMAX * FOUT];       // h = input @ W
__device__ float g_hprime[NMAX * FOUT];  // segment sum accumulator
__device__ float g_hcol[NMAX];           // h . a1l  (= input . (W a1l))
__device__ float g_ha2r[NMAX];           // h . a2r
__device__ float g_pha1r[NMAX];          // p_h . (W a1r)
__device__ float g_nha2l[NMAX];          // new_h . (W a2l)
__device__ float g_ecsm[NMAX];           // edge_col_e -> ex -> softmax result
__device__ float g_segmax[NMAX];
__device__ float g_segsum[NMAX];
__device__ float g_erowsum[NMAX];
__device__ float g_einv[NMAX];
__device__ float g_edge_e[EMAX];
__device__ float g_v1[FIN], g_v2[FIN], g_v3[FIN], g_v4[FIN];

// ---------------- small vectors: v = W @ a-halves ----------------
__global__ void k_vec(const float* __restrict__ W,
                      const float* __restrict__ a1,
                      const float* __restrict__ a2) {
    int k = threadIdx.x;  // 128 threads
    float s1 = 0.f, s2 = 0.f, s3 = 0.f, s4 = 0.f;
#pragma unroll 8
    for (int j = 0; j < FOUT; j++) {
        float w = W[k * FOUT + j];
        s1 += w * a1[j];
        s2 += w * a1[FOUT + j];
        s3 += w * a2[j];
        s4 += w * a2[FOUT + j];
    }
    g_v1[k] = s1; g_v2[k] = s2; g_v3[k] = s3; g_v4[k] = s4;
}

// ---------------- zeroing (graph-replay safe reset) ----------------
__global__ void k_zero_n(int n) {
    int i = blockIdx.x * blockDim.x + threadIdx.x;
    if (i < n) {
        g_segmax[i] = 0.f;
        g_segsum[i] = 0.f;
        g_erowsum[i] = 0.f;
    }
}
__global__ void k_zero_hp(int n4) {  // n4 = N*FOUT/4
    int i = blockIdx.x * blockDim.x + threadIdx.x;
    if (i < n4) ((float4*)g_hprime)[i] = make_float4(0.f, 0.f, 0.f, 0.f);
}

// ---------------- GEMM: h = input @ W (N x 128 x 64), 4x4 register tile ----
// 256 threads; block tile 64 rows x 64 cols; K chunked by 64.
// Thread (cg = t&15, rg = t>>4) owns rows rg*4..+3, cols cg*4..+3.
// Xs padded to 68 floats/row so the two row-groups per warp hit distinct banks.
__global__ void __launch_bounds__(256)
k_gemm(const float* __restrict__ X, const float* __restrict__ W, int n) {
    __shared__ float Ws[64][64];   // [k][c]  16 KB
    __shared__ float Xs[64][68];   // [r][k]  17.4 KB (pad 4 -> conflict-free)
    int tid = threadIdx.x;
    int cg = tid & 15;
    int rg = tid >> 4;
    long row0 = (long)blockIdx.x * 64;
    float acc[4][4] = {};

    for (int kb = 0; kb < FIN; kb += 64) {
        // stage W chunk: 64 k x 64 c = 1024 float4, 4 per thread
#pragma unroll
        for (int i = 0; i < 4; i++) {
            int idx = tid + i * 256;          // 0..1023
            int k = idx >> 4, c4 = idx & 15;
            ((float4*)&Ws[k][0])[c4] =
                ((const float4*)(W + (long)(kb + k) * FOUT))[c4];
        }
        // stage X chunk: thread t -> row t>>2, k-range (t&3)*16 .. +15
        {
            int r = tid >> 2, k0 = (tid & 3) * 16;
            long row = row0 + r;
            if (row < n) {
                const float4* src = (const float4*)(X + row * FIN + kb + k0);
#pragma unroll
                for (int j = 0; j < 4; j++)
                    *(float4*)&Xs[r][k0 + j * 4] = src[j];
            } else {
#pragma unroll
                for (int j = 0; j < 4; j++)
                    *(float4*)&Xs[r][k0 + j * 4] = make_float4(0.f, 0.f, 0.f, 0.f);
            }
        }
        __syncthreads();
#pragma unroll 8
        for (int k = 0; k < 64; k++) {
            float4 wv = *(const float4*)&Ws[k][cg * 4];
            float x0 = Xs[rg * 4 + 0][k];
            float x1 = Xs[rg * 4 + 1][k];
            float x2 = Xs[rg * 4 + 2][k];
            float x3 = Xs[rg * 4 + 3][k];
            acc[0][0] += x0 * wv.x; acc[0][1] += x0 * wv.y; acc[0][2] += x0 * wv.z; acc[0][3] += x0 * wv.w;
            acc[1][0] += x1 * wv.x; acc[1][1] += x1 * wv.y; acc[1][2] += x1 * wv.z; acc[1][3] += x1 * wv.w;
            acc[2][0] += x2 * wv.x; acc[2][1] += x2 * wv.y; acc[2][2] += x2 * wv.z; acc[2][3] += x2 * wv.w;
            acc[3][0] += x3 * wv.x; acc[3][1] += x3 * wv.y; acc[3][2] += x3 * wv.z; acc[3][3] += x3 * wv.w;
        }
        __syncthreads();
    }
#pragma unroll
    for (int r = 0; r < 4; r++) {
        long row = row0 + rg * 4 + r;
        if (row < n) {
            float4 o = make_float4(acc[r][0], acc[r][1], acc[r][2], acc[r][3]);
            ((float4*)(g_h + row * FOUT))[cg] = o;
        }
    }
}

// ---------------- per-row dot products (matrix-vector) ----------------
__global__ void k_dots(const float* __restrict__ X,
                       const float* __restrict__ P,
                       const float* __restrict__ NH, int n) {
    int warp = (blockIdx.x * blockDim.x + threadIdx.x) >> 5;
    int lane = threadIdx.x & 31;
    if (warp >= n) return;
    float4 xv = ((const float4*)(X + (long)warp * FIN))[lane];
    float4 pv = ((const float4*)(P + (long)warp * FIN))[lane];
    float4 nv = ((const float4*)(NH + (long)warp * FIN))[lane];
    float4 v1 = ((const float4*)g_v1)[lane];
    float4 v2 = ((const float4*)g_v2)[lane];
    float4 v3 = ((const float4*)g_v3)[lane];
    float4 v4 = ((const float4*)g_v4)[lane];
    float s_hcol = xv.x * v1.x + xv.y * v1.y + xv.z * v1.z + xv.w * v1.w;
    float s_ha2r = xv.x * v4.x + xv.y * v4.y + xv.z * v4.z + xv.w * v4.w;
    float s_pha1 = pv.x * v2.x + pv.y * v2.y + pv.z * v2.z + pv.w * v2.w;
    float s_nha2 = nv.x * v3.x + nv.y * v3.y + nv.z * v3.z + nv.w * v3.w;
#pragma unroll
    for (int o = 16; o > 0; o >>= 1) {
        s_hcol += __shfl_down_sync(0xFFFFFFFFu, s_hcol, o);
        s_ha2r += __shfl_down_sync(0xFFFFFFFFu, s_ha2r, o);
        s_pha1 += __shfl_down_sync(0xFFFFFFFFu, s_pha1, o);
        s_nha2 += __shfl_down_sync(0xFFFFFFFFu, s_nha2, o);
    }
    if (lane == 0) {
        g_hcol[warp] = s_hcol;
        g_ha2r[warp] = s_ha2r;
        g_pha1r[warp] = s_pha1;
        g_nha2l[warp] = s_nha2;
    }
}

// ---------------- column softmax passes ----------------
__global__ void k_col1(const int* __restrict__ edge_col0,
                       const int* __restrict__ row_i, int n) {
    int i = blockIdx.x * blockDim.x + threadIdx.x;
    if (i >= n) return;
    float cs = g_hcol[edge_col0[i]] + g_pha1r[i];
    float lr = cs > 0.f ? cs : ALPHA * cs;
    float e = expf(-lr);
    g_ecsm[i] = e;
    atomicMax((int*)&g_segmax[row_i[i]], __float_as_int(e));  // e > 0 always
}
__global__ void k_col2(const int* __restrict__ row_i, int n) {
    int i = blockIdx.x * blockDim.x + threadIdx.x;
    if (i >= n) return;
    float ex = expf(g_ecsm[i] - g_segmax[row_i[i]]);
    g_ecsm[i] = ex;
    atomicAdd(&g_segsum[row_i[i]], ex);
}
__global__ void k_col3(const int* __restrict__ row_i, int n) {
    int i = blockIdx.x * blockDim.x + threadIdx.x;
    if (i >= n) return;
    g_ecsm[i] = g_ecsm[i] / (g_segsum[row_i[i]] + 1e-16f);
}

// ---------------- edge scores + rowsum ----------------
__global__ void k_edge1(const int* __restrict__ edge0,
                        const int* __restrict__ edge1,
                        const int* __restrict__ row_resort, int E) {
    int e = blockIdx.x * blockDim.x + threadIdx.x;
    if (e >= E) return;
    int rr = row_resort[e];
    float rs = g_nha2l[rr] + g_ha2r[edge1[e]];
    float lr = rs > 0.f ? rs : ALPHA * rs;
    float ee = expf(-lr) * g_ecsm[rr];
    g_edge_e[e] = ee;
    atomicAdd(&g_erowsum[edge0[e]], ee);
}
__global__ void k_rowfix(int n) {
    int i = blockIdx.x * blockDim.x + threadIdx.x;
    if (i >= n) return;
    float s = g_erowsum[i];
    if (s == 0.f) s = 1.f;
    g_einv[i] = 1.f / s;
}

// ---------------- main scatter: h_prime += edge_e * h[edge1] ----------------
// 16 threads per edge, float4 gather + red.global.add.v4.f32 scatter (R1)
__global__ void k_edge2(const int* __restrict__ edge0,
                        const int* __restrict__ edge1,
                        float* __restrict__ att_out, int E, int write_att) {
    int e = (blockIdx.x * blockDim.x + threadIdx.x) >> 4;
    int t = threadIdx.x & 15;
    if (e >= E) return;
    int dst = edge0[e], src = edge1[e];
    float ee = g_edge_e[e];
    float4 hv = *(const float4*)(g_h + (long)src * FOUT + t * 4);
    float4 r;
    r.x = ee * hv.x; r.y = ee * hv.y; r.z = ee * hv.z; r.w = ee * hv.w;
    float* dp = g_hprime + (long)dst * FOUT + t * 4;
    asm volatile("red.global.add.v4.f32 [%0], {%1, %2, %3, %4};"
                 :: "l"(__cvta_generic_to_global(dp)),
                    "f"(r.x), "f"(r.y), "f"(r.z), "f"(r.w)
                 : "memory");
    if (t == 0 && write_att) att_out[e] = ee * g_einv[dst];
}

// ---------------- finalize: out = elu(h_prime / e_rowsum) ----------------
__global__ void k_final(float* __restrict__ out, int n) {
    int i4 = blockIdx.x * blockDim.x + threadIdx.x;  // one float4 each
    if (i4 >= n * (FOUT / 4)) return;
    int row = i4 >> 4;
    float inv = g_einv[row];
    float4 v = ((const float4*)g_hprime)[i4];
    v.x *= inv; v.y *= inv; v.z *= inv; v.w *= inv;
    v.x = v.x > 0.f ? v.x : expm1f(v.x);
    v.y = v.y > 0.f ? v.y : expm1f(v.y);
    v.z = v.z > 0.f ? v.z : expm1f(v.z);
    v.w = v.w > 0.f ? v.w : expm1f(v.w);
    ((float4*)out)[i4] = v;
}

// ---------------- copy edge indices to output as float ----------------
__global__ void k_edgecopy(const int* __restrict__ edge, float* __restrict__ out,
                           int n2e) {
    int i = blockIdx.x * blockDim.x + threadIdx.x;
    if (i < n2e) out[i] = (float)edge[i];
}

extern "C" void kernel_launch(void* const* d_in, const int* in_sizes, int n_in,
                              void* d_out, int out_size) {
    const float* input      = (const float*)d_in[0];
    const float* p_h        = (const float*)d_in[1];
    const float* new_h      = (const float*)d_in[2];
    const int*   edge       = (const int*)d_in[3];
    const int*   edge_col   = (const int*)d_in[4];
    const int*   row_i      = (const int*)d_in[5];
    const int*   row_resort = (const int*)d_in[6];
    const float* W          = (const float*)d_in[8];
    const float* a1         = (const float*)d_in[9];
    const float* a2         = (const float*)d_in[10];

    int N = in_sizes[0] / FIN;
    int E = in_sizes[3] / 2;
    const int* edge0 = edge;
    const int* edge1 = edge + E;
    float* out = (float*)d_out;

    long n64 = (long)N * FOUT;
    int full = (out_size >= (int)(n64 + 2L * E + E)) ? 1 : 0;
    float* out_edges = full ? out + n64 : nullptr;
    float* out_att   = full ? out + n64 + 2L * E : out;  // dummy if !full

    const int T = 256;
    // zero scratch (every call: graph replays)
    k_zero_n<<<(N + T - 1) / T, T>>>(N);
    k_zero_hp<<<((N * FOUT / 4) + T - 1) / T, T>>>(N * FOUT / 4);

    k_vec<<<1, 128>>>(W, a1, a2);
    k_gemm<<<(N + 63) / 64, 256>>>(input, W, N);    // launch #4 -> profiled
    k_dots<<<(N * 32 + T - 1) / T, T>>>(input, p_h, new_h, N);

    k_col1<<<(N + T - 1) / T, T>>>(edge_col, row_i, N);
    k_col2<<<(N + T - 1) / T, T>>>(row_i, N);
    k_col3<<<(N + T - 1) / T, T>>>(row_i, N);

    k_edge1<<<(E + T - 1) / T, T>>>(edge0, edge1, row_resort, E);
    k_rowfix<<<(N + T - 1) / T, T>>>(N);

    k_edge2<<<(E * 16 + T - 1) / T, T>>>(edge0, edge1, out_att, E, full);
    k_final<<<((N * FOUT / 4) + T - 1) / T, T>>>(out, N);
    if (full) {
        k_edgecopy<<<(2 * E + T - 1) / T, T>>>(edge, out_edges, 2 * E);
    }
}

// round 9
// speedup vs baseline: 1.4864x; 1.0118x over previous
#include <cuda_runtime.h>
#include <cuda_bf16.h>
#include <math.h>

#define NMAX 50000
#define EMAX 1600000
#define FIN  128
#define FOUT 64
#define ALPHA 0.2f

// ---------------- scratch (device globals; no allocation) ----------------
__device__ float g_h[NMAX * FOUT];       // h = input @ W
__device__ float g_hprime[NMAX * FOUT];  // segment sum accumulator
__device__ float g_hcol[NMAX];           // h . a1l  (= input . (W a1l))
__device__ float g_ha2r[NMAX];           // h . a2r
__device__ float g_pha1r[NMAX];          // p_h . (W a1r)
__device__ float g_nha2l[NMAX];          // new_h . (W a2l)
__device__ float g_ecsm[NMAX];           // edge_col_e -> ex -> softmax result
__device__ float g_segmax[NMAX];
__device__ float g_segsum[NMAX];
__device__ float g_erowsum[NMAX];
__device__ float g_einv[NMAX];
__device__ float g_edge_e[EMAX];
__device__ float g_v1[FIN], g_v2[FIN], g_v3[FIN], g_v4[FIN];

// ---------------- small vectors: v = W @ a-halves ----------------
__global__ void k_vec(const float* __restrict__ W,
                      const float* __restrict__ a1,
                      const float* __restrict__ a2) {
    int k = threadIdx.x;  // 128 threads
    float s1 = 0.f, s2 = 0.f, s3 = 0.f, s4 = 0.f;
#pragma unroll 8
    for (int j = 0; j < FOUT; j++) {
        float w = W[k * FOUT + j];
        s1 += w * a1[j];
        s2 += w * a1[FOUT + j];
        s3 += w * a2[j];
        s4 += w * a2[FOUT + j];
    }
    g_v1[k] = s1; g_v2[k] = s2; g_v3[k] = s3; g_v4[k] = s4;
}

// ---------------- zeroing (graph-replay safe reset) ----------------
__global__ void k_zero_n(int n) {
    int i = blockIdx.x * blockDim.x + threadIdx.x;
    if (i < n) {
        g_segmax[i] = 0.f;
        g_segsum[i] = 0.f;
        g_erowsum[i] = 0.f;
    }
}
__global__ void k_zero_hp(int n4) {  // n4 = N*FOUT/4
    int i = blockIdx.x * blockDim.x + threadIdx.x;
    if (i < n4) ((float4*)g_hprime)[i] = make_float4(0.f, 0.f, 0.f, 0.f);
}

// ---------------- GEMM: h = input @ W (N x 128 x 64), 4x4 register tile ----
// 256 threads; block tile 64 rows x 64 cols; K chunked by 64.
// Thread (cg = t&15, rg = t>>4) owns rows rg*4..+3, cols cg*4..+3.
// Inner loop unrolled by 4 over k; Xs read as LDS.128 (k-contiguous) ->
// ~3 smem wavefronts per warp-k vs 64 FMA cycles per SM-k: FMA-bound.
__global__ void __launch_bounds__(256)
k_gemm(const float* __restrict__ X, const float* __restrict__ W, int n) {
    __shared__ float Ws[64][64];   // [k][c]  16 KB
    __shared__ float Xs[64][68];   // [r][k]  17.4 KB (pitch 272B, 16B-aligned)
    int tid = threadIdx.x;
    int cg = tid & 15;
    int rg = tid >> 4;
    long row0 = (long)blockIdx.x * 64;
    float acc[4][4] = {};

    for (int kb = 0; kb < FIN; kb += 64) {
        // stage W chunk: 64 k x 64 c = 1024 float4, 4 per thread
#pragma unroll
        for (int i = 0; i < 4; i++) {
            int idx = tid + i * 256;          // 0..1023
            int k = idx >> 4, c4 = idx & 15;
            ((float4*)&Ws[k][0])[c4] =
                ((const float4*)(W + (long)(kb + k) * FOUT))[c4];
        }
        // stage X chunk: thread t -> row t>>2, k-range (t&3)*16 .. +15
        {
            int r = tid >> 2, k0 = (tid & 3) * 16;
            long row = row0 + r;
            if (row < n) {
                const float4* src = (const float4*)(X + row * FIN + kb + k0);
#pragma unroll
                for (int j = 0; j < 4; j++)
                    *(float4*)&Xs[r][k0 + j * 4] = src[j];
            } else {
#pragma unroll
                for (int j = 0; j < 4; j++)
                    *(float4*)&Xs[r][k0 + j * 4] = make_float4(0.f, 0.f, 0.f, 0.f);
            }
        }
        __syncthreads();
#pragma unroll
        for (int k4 = 0; k4 < 64; k4 += 4) {
            float4 xv0 = *(const float4*)&Xs[rg * 4 + 0][k4];
            float4 xv1 = *(const float4*)&Xs[rg * 4 + 1][k4];
            float4 xv2 = *(const float4*)&Xs[rg * 4 + 2][k4];
            float4 xv3 = *(const float4*)&Xs[rg * 4 + 3][k4];
            const float* x0 = (const float*)&xv0;
            const float* x1 = (const float*)&xv1;
            const float* x2 = (const float*)&xv2;
            const float* x3 = (const float*)&xv3;
#pragma unroll
            for (int kk = 0; kk < 4; kk++) {
                float4 wv = *(const float4*)&Ws[k4 + kk][cg * 4];
                acc[0][0] += x0[kk] * wv.x; acc[0][1] += x0[kk] * wv.y;
                acc[0][2] += x0[kk] * wv.z; acc[0][3] += x0[kk] * wv.w;
                acc[1][0] += x1[kk] * wv.x; acc[1][1] += x1[kk] * wv.y;
                acc[1][2] += x1[kk] * wv.z; acc[1][3] += x1[kk] * wv.w;
                acc[2][0] += x2[kk] * wv.x; acc[2][1] += x2[kk] * wv.y;
                acc[2][2] += x2[kk] * wv.z; acc[2][3] += x2[kk] * wv.w;
                acc[3][0] += x3[kk] * wv.x; acc[3][1] += x3[kk] * wv.y;
                acc[3][2] += x3[kk] * wv.z; acc[3][3] += x3[kk] * wv.w;
            }
        }
        __syncthreads();
    }
#pragma unroll
    for (int r = 0; r < 4; r++) {
        long row = row0 + rg * 4 + r;
        if (row < n) {
            float4 o = make_float4(acc[r][0], acc[r][1], acc[r][2], acc[r][3]);
            ((float4*)(g_h + row * FOUT))[cg] = o;
        }
    }
}

// ---------------- per-row dot products: 2 rows per warp (double MLP) -------
__global__ void k_dots(const float* __restrict__ X,
                       const float* __restrict__ P,
                       const float* __restrict__ NH, int n) {
    int warp = (blockIdx.x * blockDim.x + threadIdx.x) >> 5;
    int lane = threadIdx.x & 31;
    int r0 = warp * 2;
    if (r0 >= n) return;
    int r1 = r0 + 1 < n ? r0 + 1 : r0;   // guard (n even -> never taken)
    float4 xv0 = ((const float4*)(X + (long)r0 * FIN))[lane];
    float4 pv0 = ((const float4*)(P + (long)r0 * FIN))[lane];
    float4 nv0 = ((const float4*)(NH + (long)r0 * FIN))[lane];
    float4 xv1 = ((const float4*)(X + (long)r1 * FIN))[lane];
    float4 pv1 = ((const float4*)(P + (long)r1 * FIN))[lane];
    float4 nv1 = ((const float4*)(NH + (long)r1 * FIN))[lane];
    float4 v1 = ((const float4*)g_v1)[lane];
    float4 v2 = ((const float4*)g_v2)[lane];
    float4 v3 = ((const float4*)g_v3)[lane];
    float4 v4 = ((const float4*)g_v4)[lane];
    float a0 = xv0.x * v1.x + xv0.y * v1.y + xv0.z * v1.z + xv0.w * v1.w;
    float b0 = xv0.x * v4.x + xv0.y * v4.y + xv0.z * v4.z + xv0.w * v4.w;
    float c0 = pv0.x * v2.x + pv0.y * v2.y + pv0.z * v2.z + pv0.w * v2.w;
    float d0 = nv0.x * v3.x + nv0.y * v3.y + nv0.z * v3.z + nv0.w * v3.w;
    float a1 = xv1.x * v1.x + xv1.y * v1.y + xv1.z * v1.z + xv1.w * v1.w;
    float b1 = xv1.x * v4.x + xv1.y * v4.y + xv1.z * v4.z + xv1.w * v4.w;
    float c1 = pv1.x * v2.x + pv1.y * v2.y + pv1.z * v2.z + pv1.w * v2.w;
    float d1 = nv1.x * v3.x + nv1.y * v3.y + nv1.z * v3.z + nv1.w * v3.w;
#pragma unroll
    for (int o = 16; o > 0; o >>= 1) {
        a0 += __shfl_down_sync(0xFFFFFFFFu, a0, o);
        b0 += __shfl_down_sync(0xFFFFFFFFu, b0, o);
        c0 += __shfl_down_sync(0xFFFFFFFFu, c0, o);
        d0 += __shfl_down_sync(0xFFFFFFFFu, d0, o);
        a1 += __shfl_down_sync(0xFFFFFFFFu, a1, o);
        b1 += __shfl_down_sync(0xFFFFFFFFu, b1, o);
        c1 += __shfl_down_sync(0xFFFFFFFFu, c1, o);
        d1 += __shfl_down_sync(0xFFFFFFFFu, d1, o);
    }
    if (lane == 0) {
        g_hcol[r0] = a0; g_ha2r[r0] = b0; g_pha1r[r0] = c0; g_nha2l[r0] = d0;
        if (r1 != r0) {
            g_hcol[r1] = a1; g_ha2r[r1] = b1; g_pha1r[r1] = c1; g_nha2l[r1] = d1;
        }
    }
}

// ---------------- column softmax passes ----------------
__global__ void k_col1(const int* __restrict__ edge_col0,
                       const int* __restrict__ row_i, int n) {
    int i = blockIdx.x * blockDim.x + threadIdx.x;
    if (i >= n) return;
    float cs = g_hcol[edge_col0[i]] + g_pha1r[i];
    float lr = cs > 0.f ? cs : ALPHA * cs;
    float e = expf(-lr);
    g_ecsm[i] = e;
    atomicMax((int*)&g_segmax[row_i[i]], __float_as_int(e));  // e > 0 always
}
__global__ void k_col2(const int* __restrict__ row_i, int n) {
    int i = blockIdx.x * blockDim.x + threadIdx.x;
    if (i >= n) return;
    float ex = expf(g_ecsm[i] - g_segmax[row_i[i]]);
    g_ecsm[i] = ex;
    atomicAdd(&g_segsum[row_i[i]], ex);
}
__global__ void k_col3(const int* __restrict__ row_i, int n) {
    int i = blockIdx.x * blockDim.x + threadIdx.x;
    if (i >= n) return;
    g_ecsm[i] = g_ecsm[i] / (g_segsum[row_i[i]] + 1e-16f);
}

// ---------------- edge scores + rowsum ----------------
__global__ void k_edge1(const int* __restrict__ edge0,
                        const int* __restrict__ edge1,
                        const int* __restrict__ row_resort, int E) {
    int e = blockIdx.x * blockDim.x + threadIdx.x;
    if (e >= E) return;
    int rr = row_resort[e];
    float rs = g_nha2l[rr] + g_ha2r[edge1[e]];
    float lr = rs > 0.f ? rs : ALPHA * rs;
    float ee = expf(-lr) * g_ecsm[rr];
    g_edge_e[e] = ee;
    atomicAdd(&g_erowsum[edge0[e]], ee);
}
__global__ void k_rowfix(int n) {
    int i = blockIdx.x * blockDim.x + threadIdx.x;
    if (i >= n) return;
    float s = g_erowsum[i];
    if (s == 0.f) s = 1.f;
    g_einv[i] = 1.f / s;
}

// ---------------- main scatter: h_prime += edge_e * h[edge1] ----------------
// 16 threads per edge, float4 gather + red.global.add.v4.f32 scatter (R1)
__global__ void k_edge2(const int* __restrict__ edge0,
                        const int* __restrict__ edge1,
                        float* __restrict__ att_out, int E, int write_att) {
    int e = (blockIdx.x * blockDim.x + threadIdx.x) >> 4;
    int t = threadIdx.x & 15;
    if (e >= E) return;
    int dst = edge0[e], src = edge1[e];
    float ee = g_edge_e[e];
    float4 hv = *(const float4*)(g_h + (long)src * FOUT + t * 4);
    float4 r;
    r.x = ee * hv.x; r.y = ee * hv.y; r.z = ee * hv.z; r.w = ee * hv.w;
    float* dp = g_hprime + (long)dst * FOUT + t * 4;
    asm volatile("red.global.add.v4.f32 [%0], {%1, %2, %3, %4};"
                 :: "l"(__cvta_generic_to_global(dp)),
                    "f"(r.x), "f"(r.y), "f"(r.z), "f"(r.w)
                 : "memory");
    if (t == 0 && write_att) att_out[e] = ee * g_einv[dst];
}

// ---------------- finalize: out = elu(h_prime / e_rowsum) ----------------
__global__ void k_final(float* __restrict__ out, int n) {
    int i4 = blockIdx.x * blockDim.x + threadIdx.x;  // one float4 each
    if (i4 >= n * (FOUT / 4)) return;
    int row = i4 >> 4;
    float inv = g_einv[row];
    float4 v = ((const float4*)g_hprime)[i4];
    v.x *= inv; v.y *= inv; v.z *= inv; v.w *= inv;
    v.x = v.x > 0.f ? v.x : expm1f(v.x);
    v.y = v.y > 0.f ? v.y : expm1f(v.y);
    v.z = v.z > 0.f ? v.z : expm1f(v.z);
    v.w = v.w > 0.f ? v.w : expm1f(v.w);
    ((float4*)out)[i4] = v;
}

// ---------------- copy edge indices to output as float ----------------
__global__ void k_edgecopy(const int* __restrict__ edge, float* __restrict__ out,
                           int n2e) {
    int i = blockIdx.x * blockDim.x + threadIdx.x;
    if (i < n2e) out[i] = (float)edge[i];
}

extern "C" void kernel_launch(void* const* d_in, const int* in_sizes, int n_in,
                              void* d_out, int out_size) {
    const float* input      = (const float*)d_in[0];
    const float* p_h        = (const float*)d_in[1];
    const float* new_h      = (const float*)d_in[2];
    const int*   edge       = (const int*)d_in[3];
    const int*   edge_col   = (const int*)d_in[4];
    const int*   row_i      = (const int*)d_in[5];
    const int*   row_resort = (const int*)d_in[6];
    const float* W          = (const float*)d_in[8];
    const float* a1         = (const float*)d_in[9];
    const float* a2         = (const float*)d_in[10];

    int N = in_sizes[0] / FIN;
    int E = in_sizes[3] / 2;
    const int* edge0 = edge;
    const int* edge1 = edge + E;
    float* out = (float*)d_out;

    long n64 = (long)N * FOUT;
    int full = (out_size >= (int)(n64 + 2L * E + E)) ? 1 : 0;
    float* out_edges = full ? out + n64 : nullptr;
    float* out_att   = full ? out + n64 + 2L * E : out;  // dummy if !full

    const int T = 256;
    // zero scratch (every call: graph replays)
    k_zero_n<<<(N + T - 1) / T, T>>>(N);
    k_zero_hp<<<((N * FOUT / 4) + T - 1) / T, T>>>(N * FOUT / 4);

    k_vec<<<1, 128>>>(W, a1, a2);
    k_gemm<<<(N + 63) / 64, 256>>>(input, W, N);    // launch #4 -> profiled
    k_dots<<<(((N + 1) / 2) * 32 + T - 1) / T, T>>>(input, p_h, new_h, N);

    k_col1<<<(N + T - 1) / T, T>>>(edge_col, row_i, N);
    k_col2<<<(N + T - 1) / T, T>>>(row_i, N);
    k_col3<<<(N + T - 1) / T, T>>>(row_i, N);

    k_edge1<<<(E + T - 1) / T, T>>>(edge0, edge1, row_resort, E);
    k_rowfix<<<(N + T - 1) / T, T>>>(N);

    k_edge2<<<(E * 16 + T - 1) / T, T>>>(edge0, edge1, out_att, E, full);
    k_final<<<((N * FOUT / 4) + T - 1) / T, T>>>(out, N);
    if (full) {
        k_edgecopy<<<(2 * E + T - 1) / T, T>>>(edge, out_edges, 2 * E);
    }
}

// round 10
// speedup vs baseline: 1.6043x; 1.0793x over previous
#include <cuda_runtime.h>
#include <cuda_fp16.h>
#include <mma.h>
#include <math.h>

using namespace nvcuda;

#define NMAX 50000
#define NPAD 50176                 // padded rows so wmma tail stores stay in-bounds
#define EMAX 1600000
#define FIN  128
#define FOUT 64
#define ALPHA 0.2f

// ---------------- scratch (device globals; no allocation) ----------------
__device__ float g_h[NPAD * FOUT];       // h = input @ W (fp32; padded tail)
__device__ float g_hprime[NMAX * FOUT];  // segment sum accumulator
__device__ float g_hcol[NMAX];           // h . a1l  (= input . (W a1l))
__device__ float g_ha2r[NMAX];           // h . a2r
__device__ float g_pha1r[NMAX];          // p_h . (W a1r)
__device__ float g_nha2l[NMAX];          // new_h . (W a2l)
__device__ float g_ecsm[NMAX];           // edge_col_e -> ex -> softmax result
__device__ float g_segmax[NMAX];
__device__ float g_segsum[NMAX];
__device__ float g_erowsum[NMAX];
__device__ float g_einv[NMAX];
__device__ float g_edge_e[EMAX];
__device__ float g_v1[FIN], g_v2[FIN], g_v3[FIN], g_v4[FIN];

// ---------------- small vectors: v = W @ a-halves ----------------
__global__ void k_vec(const float* __restrict__ W,
                      const float* __restrict__ a1,
                      const float* __restrict__ a2) {
    int k = threadIdx.x;  // 128 threads
    float s1 = 0.f, s2 = 0.f, s3 = 0.f, s4 = 0.f;
#pragma unroll 8
    for (int j = 0; j < FOUT; j++) {
        float w = W[k * FOUT + j];
        s1 += w * a1[j];
        s2 += w * a1[FOUT + j];
        s3 += w * a2[j];
        s4 += w * a2[FOUT + j];
    }
    g_v1[k] = s1; g_v2[k] = s2; g_v3[k] = s3; g_v4[k] = s4;
}

// ---------------- zeroing (graph-replay safe reset) ----------------
__global__ void k_zero_n(int n) {
    int i = blockIdx.x * blockDim.x + threadIdx.x;
    if (i < n) {
        g_segmax[i] = 0.f;
        g_segsum[i] = 0.f;
        g_erowsum[i] = 0.f;
    }
}
__global__ void k_zero_hp(int n4) {  // n4 = N*FOUT/4
    int i = blockIdx.x * blockDim.x + threadIdx.x;
    if (i < n4) ((float4*)g_hprime)[i] = make_float4(0.f, 0.f, 0.f, 0.f);
}

// ---------------- GEMM: h = input @ W via fp16 tensor cores ----------------
// 256 threads = 8 warps (4 row-groups x 2 col-groups). Block tile 128x64,
// K chunked by 64. X/W quantized to fp16 in smem; fp32 accumulate.
#define XS_LD 72   // 64 + 8 pad halves; 144 B row stride (16B multiple)
#define WS_LD 72
__global__ void __launch_bounds__(256)
k_gemm(const float* __restrict__ X, const float* __restrict__ W, int n) {
    __shared__ __half Xs[128][XS_LD];  // 18.4 KB  [row][k]
    __shared__ __half Ws[64][WS_LD];   //  9.2 KB  [k][col]
    int tid = threadIdx.x;
    int warp = tid >> 5;
    int wr = warp >> 1;    // 0..3 -> rows wr*32..+31
    int wc = warp & 1;     // 0..1 -> cols wc*32..+31
    long row0 = (long)blockIdx.x * 128;

    wmma::fragment<wmma::accumulator, 16, 16, 16, float> acc[2][2];
#pragma unroll
    for (int i = 0; i < 2; i++)
#pragma unroll
        for (int j = 0; j < 2; j++)
            wmma::fill_fragment(acc[i][j], 0.f);

    for (int kb = 0; kb < FIN; kb += 64) {
        // stage X chunk: 128 rows x 64 k = 2048 float4, 8 per thread
#pragma unroll
        for (int i = 0; i < 8; i++) {
            int idx = tid + i * 256;       // 0..2047
            int r = idx >> 4;
            int k0 = (idx & 15) * 4;
            long row = row0 + r;
            __half2 h0, h1;
            if (row < n) {
                float4 v = *(const float4*)(X + row * FIN + kb + k0);
                h0 = __floats2half2_rn(v.x, v.y);
                h1 = __floats2half2_rn(v.z, v.w);
            } else {
                h0 = __floats2half2_rn(0.f, 0.f);
                h1 = h0;
            }
            __half2* dst = (__half2*)&Xs[r][k0];
            dst[0] = h0; dst[1] = h1;
        }
        // stage W chunk: 64 k x 64 c = 1024 float4, 4 per thread
#pragma unroll
        for (int i = 0; i < 4; i++) {
            int idx = tid + i * 256;       // 0..1023
            int k = idx >> 4;
            int c0 = (idx & 15) * 4;
            float4 v = *(const float4*)(W + (long)(kb + k) * FOUT + c0);
            __half2* dst = (__half2*)&Ws[k][c0];
            dst[0] = __floats2half2_rn(v.x, v.y);
            dst[1] = __floats2half2_rn(v.z, v.w);
        }
        __syncthreads();
#pragma unroll
        for (int k16 = 0; k16 < 64; k16 += 16) {
            wmma::fragment<wmma::matrix_a, 16, 16, 16, __half, wmma::row_major> a0, a1;
            wmma::fragment<wmma::matrix_b, 16, 16, 16, __half, wmma::row_major> b0, b1;
            wmma::load_matrix_sync(a0, &Xs[wr * 32][k16], XS_LD);
            wmma::load_matrix_sync(a1, &Xs[wr * 32 + 16][k16], XS_LD);
            wmma::load_matrix_sync(b0, &Ws[k16][wc * 32], WS_LD);
            wmma::load_matrix_sync(b1, &Ws[k16][wc * 32 + 16], WS_LD);
            wmma::mma_sync(acc[0][0], a0, b0, acc[0][0]);
            wmma::mma_sync(acc[0][1], a0, b1, acc[0][1]);
            wmma::mma_sync(acc[1][0], a1, b0, acc[1][0]);
            wmma::mma_sync(acc[1][1], a1, b1, acc[1][1]);
        }
        __syncthreads();
    }
    // store (padding rows absorb the tail; g_h has NPAD rows)
#pragma unroll
    for (int i = 0; i < 2; i++)
#pragma unroll
        for (int j = 0; j < 2; j++) {
            float* dst = g_h + (row0 + wr * 32 + i * 16) * FOUT + wc * 32 + j * 16;
            wmma::store_matrix_sync(dst, acc[i][j], FOUT, wmma::mem_row_major);
        }
}

// ---------------- per-row dot products: 2 rows per warp (double MLP) -------
__global__ void k_dots(const float* __restrict__ X,
                       const float* __restrict__ P,
                       const float* __restrict__ NH, int n) {
    int warp = (blockIdx.x * blockDim.x + threadIdx.x) >> 5;
    int lane = threadIdx.x & 31;
    int r0 = warp * 2;
    if (r0 >= n) return;
    int r1 = r0 + 1 < n ? r0 + 1 : r0;
    float4 xv0 = ((const float4*)(X + (long)r0 * FIN))[lane];
    float4 pv0 = ((const float4*)(P + (long)r0 * FIN))[lane];
    float4 nv0 = ((const float4*)(NH + (long)r0 * FIN))[lane];
    float4 xv1 = ((const float4*)(X + (long)r1 * FIN))[lane];
    float4 pv1 = ((const float4*)(P + (long)r1 * FIN))[lane];
    float4 nv1 = ((const float4*)(NH + (long)r1 * FIN))[lane];
    float4 v1 = ((const float4*)g_v1)[lane];
    float4 v2 = ((const float4*)g_v2)[lane];
    float4 v3 = ((const float4*)g_v3)[lane];
    float4 v4 = ((const float4*)g_v4)[lane];
    float a0 = xv0.x * v1.x + xv0.y * v1.y + xv0.z * v1.z + xv0.w * v1.w;
    float b0 = xv0.x * v4.x + xv0.y * v4.y + xv0.z * v4.z + xv0.w * v4.w;
    float c0 = pv0.x * v2.x + pv0.y * v2.y + pv0.z * v2.z + pv0.w * v2.w;
    float d0 = nv0.x * v3.x + nv0.y * v3.y + nv0.z * v3.z + nv0.w * v3.w;
    float a1 = xv1.x * v1.x + xv1.y * v1.y + xv1.z * v1.z + xv1.w * v1.w;
    float b1 = xv1.x * v4.x + xv1.y * v4.y + xv1.z * v4.z + xv1.w * v4.w;
    float c1 = pv1.x * v2.x + pv1.y * v2.y + pv1.z * v2.z + pv1.w * v2.w;
    float d1 = nv1.x * v3.x + nv1.y * v3.y + nv1.z * v3.z + nv1.w * v3.w;
#pragma unroll
    for (int o = 16; o > 0; o >>= 1) {
        a0 += __shfl_down_sync(0xFFFFFFFFu, a0, o);
        b0 += __shfl_down_sync(0xFFFFFFFFu, b0, o);
        c0 += __shfl_down_sync(0xFFFFFFFFu, c0, o);
        d0 += __shfl_down_sync(0xFFFFFFFFu, d0, o);
        a1 += __shfl_down_sync(0xFFFFFFFFu, a1, o);
        b1 += __shfl_down_sync(0xFFFFFFFFu, b1, o);
        c1 += __shfl_down_sync(0xFFFFFFFFu, c1, o);
        d1 += __shfl_down_sync(0xFFFFFFFFu, d1, o);
    }
    if (lane == 0) {
        g_hcol[r0] = a0; g_ha2r[r0] = b0; g_pha1r[r0] = c0; g_nha2l[r0] = d0;
        if (r1 != r0) {
            g_hcol[r1] = a1; g_ha2r[r1] = b1; g_pha1r[r1] = c1; g_nha2l[r1] = d1;
        }
    }
}

// ---------------- column softmax passes ----------------
__global__ void k_col1(const int* __restrict__ edge_col0,
                       const int* __restrict__ row_i, int n) {
    int i = blockIdx.x * blockDim.x + threadIdx.x;
    if (i >= n) return;
    float cs = g_hcol[edge_col0[i]] + g_pha1r[i];
    float lr = cs > 0.f ? cs : ALPHA * cs;
    float e = expf(-lr);
    g_ecsm[i] = e;
    atomicMax((int*)&g_segmax[row_i[i]], __float_as_int(e));  // e > 0 always
}
__global__ void k_col2(const int* __restrict__ row_i, int n) {
    int i = blockIdx.x * blockDim.x + threadIdx.x;
    if (i >= n) return;
    float ex = expf(g_ecsm[i] - g_segmax[row_i[i]]);
    g_ecsm[i] = ex;
    atomicAdd(&g_segsum[row_i[i]], ex);
}
__global__ void k_col3(const int* __restrict__ row_i, int n) {
    int i = blockIdx.x * blockDim.x + threadIdx.x;
    if (i >= n) return;
    g_ecsm[i] = g_ecsm[i] / (g_segsum[row_i[i]] + 1e-16f);
}

// ---------------- edge scores + rowsum ----------------
__global__ void k_edge1(const int* __restrict__ edge0,
                        const int* __restrict__ edge1,
                        const int* __restrict__ row_resort, int E) {
    int e = blockIdx.x * blockDim.x + threadIdx.x;
    if (e >= E) return;
    int rr = row_resort[e];
    float rs = g_nha2l[rr] + g_ha2r[edge1[e]];
    float lr = rs > 0.f ? rs : ALPHA * rs;
    float ee = expf(-lr) * g_ecsm[rr];
    g_edge_e[e] = ee;
    atomicAdd(&g_erowsum[edge0[e]], ee);
}
__global__ void k_rowfix(int n) {
    int i = blockIdx.x * blockDim.x + threadIdx.x;
    if (i >= n) return;
    float s = g_erowsum[i];
    if (s == 0.f) s = 1.f;
    g_einv[i] = 1.f / s;
}

// ---------------- main scatter: h_prime += edge_e * h[edge1] ----------------
// 16 threads per edge, float4 gather + red.global.add.v4.f32 scatter (R1)
__global__ void k_edge2(const int* __restrict__ edge0,
                        const int* __restrict__ edge1,
                        float* __restrict__ att_out, int E, int write_att) {
    int e = (blockIdx.x * blockDim.x + threadIdx.x) >> 4;
    int t = threadIdx.x & 15;
    if (e >= E) return;
    int dst = edge0[e], src = edge1[e];
    float ee = g_edge_e[e];
    float4 hv = *(const float4*)(g_h + (long)src * FOUT + t * 4);
    float4 r;
    r.x = ee * hv.x; r.y = ee * hv.y; r.z = ee * hv.z; r.w = ee * hv.w;
    float* dp = g_hprime + (long)dst * FOUT + t * 4;
    asm volatile("red.global.add.v4.f32 [%0], {%1, %2, %3, %4};"
                 :: "l"(__cvta_generic_to_global(dp)),
                    "f"(r.x), "f"(r.y), "f"(r.z), "f"(r.w)
                 : "memory");
    if (t == 0 && write_att) att_out[e] = ee * g_einv[dst];
}

// ---------------- finalize: out = elu(h_prime / e_rowsum) ----------------
__global__ void k_final(float* __restrict__ out, int n) {
    int i4 = blockIdx.x * blockDim.x + threadIdx.x;  // one float4 each
    if (i4 >= n * (FOUT / 4)) return;
    int row = i4 >> 4;
    float inv = g_einv[row];
    float4 v = ((const float4*)g_hprime)[i4];
    v.x *= inv; v.y *= inv; v.z *= inv; v.w *= inv;
    v.x = v.x > 0.f ? v.x : expm1f(v.x);
    v.y = v.y > 0.f ? v.y : expm1f(v.y);
    v.z = v.z > 0.f ? v.z : expm1f(v.z);
    v.w = v.w > 0.f ? v.w : expm1f(v.w);
    ((float4*)out)[i4] = v;
}

// ---------------- copy edge indices to output as float ----------------
__global__ void k_edgecopy(const int* __restrict__ edge, float* __restrict__ out,
                           int n2e) {
    int i = blockIdx.x * blockDim.x + threadIdx.x;
    if (i < n2e) out[i] = (float)edge[i];
}

extern "C" void kernel_launch(void* const* d_in, const int* in_sizes, int n_in,
                              void* d_out, int out_size) {
    const float* input      = (const float*)d_in[0];
    const float* p_h        = (const float*)d_in[1];
    const float* new_h      = (const float*)d_in[2];
    const int*   edge       = (const int*)d_in[3];
    const int*   edge_col   = (const int*)d_in[4];
    const int*   row_i      = (const int*)d_in[5];
    const int*   row_resort = (const int*)d_in[6];
    const float* W          = (const float*)d_in[8];
    const float* a1         = (const float*)d_in[9];
    const float* a2         = (const float*)d_in[10];

    int N = in_sizes[0] / FIN;
    int E = in_sizes[3] / 2;
    const int* edge0 = edge;
    const int* edge1 = edge + E;
    float* out = (float*)d_out;

    long n64 = (long)N * FOUT;
    int full = (out_size >= (int)(n64 + 2L * E + E)) ? 1 : 0;
    float* out_edges = full ? out + n64 : nullptr;
    float* out_att   = full ? out + n64 + 2L * E : out;  // dummy if !full

    const int T = 256;
    // zero scratch (every call: graph replays)
    k_zero_n<<<(N + T - 1) / T, T>>>(N);
    k_zero_hp<<<((N * FOUT / 4) + T - 1) / T, T>>>(N * FOUT / 4);

    k_vec<<<1, 128>>>(W, a1, a2);
    k_gemm<<<(N + 127) / 128, 256>>>(input, W, N);   // launch #4 -> profiled
    k_dots<<<(((N + 1) / 2) * 32 + T - 1) / T, T>>>(input, p_h, new_h, N);

    k_col1<<<(N + T - 1) / T, T>>>(edge_col, row_i, N);
    k_col2<<<(N + T - 1) / T, T>>>(row_i, N);
    k_col3<<<(N + T - 1) / T, T>>>(row_i, N);

    k_edge1<<<(E + T - 1) / T, T>>>(edge0, edge1, row_resort, E);
    k_rowfix<<<(N + T - 1) / T, T>>>(N);

    k_edge2<<<(E * 16 + T - 1) / T, T>>>(edge0, edge1, out_att, E, full);
    k_final<<<((N * FOUT / 4) + T - 1) / T, T>>>(out, N);
    if (full) {
        k_edgecopy<<<(2 * E + T - 1) / T, T>>>(edge, out_edges, 2 * E);
    }
}